// round 1
// baseline (speedup 1.0000x reference)
#include <cuda_runtime.h>
#include <math.h>

#define T_TOK 16384
#define HDIM  4096
#define NEXP  256
#define NGRP  8
#define TOPK  8
#define TOPK_GRP 4

#define BM 128
#define BN 64
#define BK 16

// 16 MB scratch for router logits (static device array: allocation-free)
__device__ float g_logits[(size_t)T_TOK * NEXP];

__device__ __forceinline__ unsigned long long pack2(float a, float b) {
    unsigned long long r;
    asm("mov.b64 %0, {%1, %2};" : "=l"(r) : "f"(a), "f"(b));
    return r;
}
__device__ __forceinline__ float2 unpack2(unsigned long long v) {
    float2 r;
    asm("mov.b64 {%0, %1}, %2;" : "=f"(r.x), "=f"(r.y) : "l"(v));
    return r;
}
__device__ __forceinline__ void fma2(unsigned long long& acc, unsigned long long a,
                                     unsigned long long b) {
    asm("fma.rn.f32x2 %0, %1, %2, %0;" : "+l"(acc) : "l"(a), "l"(b));
}

// ---------------------------------------------------------------------------
// GEMM: logits[m][e] = dot(x[m,:], W[e,:])  fp32, packed-f32x2 FMA inner loop
// grid: (NEXP/BN, T_TOK/BM), 256 threads
// ---------------------------------------------------------------------------
__global__ __launch_bounds__(256) void gemm_kernel(const float* __restrict__ A,
                                                   const float* __restrict__ W) {
    __shared__ float As[BK][BM + 4];                   // A^T tile
    __shared__ unsigned long long Bs[BK][BN + 2];      // B^T tile, each val duplicated (v,v)

    const int tid   = threadIdx.x;
    const int ntile = blockIdx.x;
    const int mtile = blockIdx.y;

    const float* Ab = A + (size_t)mtile * BM * HDIM;
    const float* Wb = W + (size_t)ntile * BN * HDIM;

    const int lrow = tid >> 2;         // 0..63
    const int lcol = (tid & 3) * 4;    // 0,4,8,12

    const float* pa0 = Ab + (size_t)lrow * HDIM + lcol;
    const float* pa1 = Ab + (size_t)(lrow + 64) * HDIM + lcol;
    const float* pb  = Wb + (size_t)lrow * HDIM + lcol;

    // prefetch tile 0
    float4 ra0 = *(const float4*)pa0;
    float4 ra1 = *(const float4*)pa1;
    float4 rb  = *(const float4*)pb;

    const int tx = tid & 15;   // n sub-tile: 16 x 4 cols
    const int ty = tid >> 4;   // m sub-tile: 16 x 8 rows

    unsigned long long acc[4][4];
#pragma unroll
    for (int p = 0; p < 4; p++)
#pragma unroll
        for (int j = 0; j < 4; j++) acc[p][j] = 0ull;

    for (int k0 = 0; k0 < HDIM; k0 += BK) {
        __syncthreads();
        As[lcol + 0][lrow] = ra0.x;
        As[lcol + 1][lrow] = ra0.y;
        As[lcol + 2][lrow] = ra0.z;
        As[lcol + 3][lrow] = ra0.w;
        As[lcol + 0][lrow + 64] = ra1.x;
        As[lcol + 1][lrow + 64] = ra1.y;
        As[lcol + 2][lrow + 64] = ra1.z;
        As[lcol + 3][lrow + 64] = ra1.w;
        Bs[lcol + 0][lrow] = pack2(rb.x, rb.x);
        Bs[lcol + 1][lrow] = pack2(rb.y, rb.y);
        Bs[lcol + 2][lrow] = pack2(rb.z, rb.z);
        Bs[lcol + 3][lrow] = pack2(rb.w, rb.w);
        __syncthreads();

        const int kn = k0 + BK;
        if (kn < HDIM) {   // prefetch next tile (LDGs overlap compute below)
            ra0 = *(const float4*)(pa0 + kn);
            ra1 = *(const float4*)(pa1 + kn);
            rb  = *(const float4*)(pb + kn);
        }

#pragma unroll
        for (int k = 0; k < BK; k++) {
            const unsigned long long* ap =
                (const unsigned long long*)&As[k][ty * 8];
            unsigned long long a2[4] = {ap[0], ap[1], ap[2], ap[3]};
            const unsigned long long* bp = &Bs[k][tx * 4];
            unsigned long long b2[4] = {bp[0], bp[1], bp[2], bp[3]};
#pragma unroll
            for (int p = 0; p < 4; p++)
#pragma unroll
                for (int j = 0; j < 4; j++) fma2(acc[p][j], a2[p], b2[j]);
        }
    }

    // epilogue: acc[p][j] = rows (ty*8+2p, ty*8+2p+1), col tx*4+j
    const int col0 = ntile * BN + tx * 4;
#pragma unroll
    for (int p = 0; p < 4; p++) {
        float2 f0 = unpack2(acc[p][0]);
        float2 f1 = unpack2(acc[p][1]);
        float2 f2 = unpack2(acc[p][2]);
        float2 f3 = unpack2(acc[p][3]);
        const int m0 = mtile * BM + ty * 8 + 2 * p;
        float4 lo = make_float4(f0.x, f1.x, f2.x, f3.x);
        float4 hi = make_float4(f0.y, f1.y, f2.y, f3.y);
        *(float4*)&g_logits[(size_t)m0 * NEXP + col0]       = lo;
        *(float4*)&g_logits[(size_t)(m0 + 1) * NEXP + col0] = hi;
    }
}

// ---------------------------------------------------------------------------
// Routing: one warp per token. Exact reference semantics:
//   scores = sigmoid(logits); sc = scores + bias
//   group score = sum of top-2 sc in each group of 32; top-4 groups
//   masked = in-group ? sc : 0.0 ; top-8 (lowest index wins ties, like lax.top_k)
//   weights = scores[idx]; w = (w / (sum + 1e-20)) * 2.5
// ---------------------------------------------------------------------------
__global__ __launch_bounds__(256) void route_kernel(const float* __restrict__ bias,
                                                    void* __restrict__ out,
                                                    int mode) {
    const int warp = (blockIdx.x * blockDim.x + threadIdx.x) >> 5;
    const int lane = threadIdx.x & 31;
    if (warp >= T_TOK) return;

    const float* lg = g_logits + (size_t)warp * NEXP + lane * 8;
    float4 x0 = *(const float4*)lg;
    float4 x1 = *(const float4*)(lg + 4);
    float xs[8] = {x0.x, x0.y, x0.z, x0.w, x1.x, x1.y, x1.z, x1.w};

    const float* bp = bias + lane * 8;
    float4 b0 = *(const float4*)bp;
    float4 b1 = *(const float4*)(bp + 4);
    float bs[8] = {b0.x, b0.y, b0.z, b0.w, b1.x, b1.y, b1.z, b1.w};

    float s[8], sc[8];
#pragma unroll
    for (int j = 0; j < 8; j++) {
        s[j]  = 1.0f / (1.0f + expf(-xs[j]));
        sc[j] = s[j] + bs[j];
    }

    // per-lane top-2 of its 8 sc values
    float m1 = -1e30f, m2 = -1e30f;
#pragma unroll
    for (int j = 0; j < 8; j++) {
        float x = sc[j];
        if (x > m1) { m2 = m1; m1 = x; }
        else if (x > m2) { m2 = x; }
    }
    // merge across the 4 lanes of each group (experts lane*8.. => group = lane/4)
#pragma unroll
    for (int d = 1; d <= 2; d <<= 1) {
        float o1 = __shfl_xor_sync(0xffffffffu, m1, d);
        float o2 = __shfl_xor_sync(0xffffffffu, m2, d);
        float n2 = fmaxf(fminf(m1, o1), fmaxf(m2, o2));
        m1 = fmaxf(m1, o1);
        m2 = n2;
    }
    float gs = m1 + m2;

    float gsv[8];
#pragma unroll
    for (int g = 0; g < 8; g++) gsv[g] = __shfl_sync(0xffffffffu, gs, g * 4);

    // top-4 groups, lowest index on ties (strict > keeps first)
    unsigned gsel = 0;
#pragma unroll
    for (int r = 0; r < TOPK_GRP; r++) {
        float best = -1e30f; int bi = 0;
#pragma unroll
        for (int g = 0; g < 8; g++) {
            float v = ((gsel >> g) & 1u) ? -1e30f : gsv[g];
            if (v > best) { best = v; bi = g; }
        }
        gsel |= 1u << bi;
    }

    const bool insel = (gsel >> (lane >> 2)) & 1u;
    float mv[8];
#pragma unroll
    for (int j = 0; j < 8; j++) mv[j] = insel ? sc[j] : 0.0f;

    int   oi[8];
    float ow[8];
#pragma unroll
    for (int r = 0; r < TOPK; r++) {
        // local argmax (lowest j wins ties via strict >)
        float lb = mv[0]; int lj = 0;
#pragma unroll
        for (int j = 1; j < 8; j++)
            if (mv[j] > lb) { lb = mv[j]; lj = j; }
        float bv = lb;
        int   be = lane * 8 + lj;
        // warp argmax, lexicographic (value desc, index asc)
#pragma unroll
        for (int off = 16; off >= 1; off >>= 1) {
            float ov = __shfl_xor_sync(0xffffffffu, bv, off);
            int   oe = __shfl_xor_sync(0xffffffffu, be, off);
            if (ov > bv || (ov == bv && oe < be)) { bv = ov; be = oe; }
        }
        oi[r] = be;
        const int jj = be & 7;
        float sj = s[0];
#pragma unroll
        for (int j = 1; j < 8; j++)
            if (jj == j) sj = s[j];
        ow[r] = __shfl_sync(0xffffffffu, sj, be >> 3);
        if (lane == (be >> 3)) {
#pragma unroll
            for (int j = 0; j < 8; j++)
                if (jj == j) mv[j] = -1e30f;
        }
    }

    if (lane == 0) {
        float sum = 0.0f;
#pragma unroll
        for (int r = 0; r < TOPK; r++) sum += ow[r];
        const float den = sum + 1e-20f;
        if (mode == 0) {
            // concat layout: [indices as f32 | weights], each (T, 8) row-major
            float* of = (float*)out;
#pragma unroll
            for (int r = 0; r < TOPK; r++) {
                of[(size_t)warp * TOPK + r] = (float)oi[r];
                of[(size_t)T_TOK * TOPK + (size_t)warp * TOPK + r] =
                    (ow[r] / den) * 2.5f;
            }
        } else {
            int* op = (int*)out;
#pragma unroll
            for (int r = 0; r < TOPK; r++) op[(size_t)warp * TOPK + r] = oi[r];
        }
    }
}

extern "C" void kernel_launch(void* const* d_in, const int* in_sizes, int n_in,
                              void* d_out, int out_size) {
    const float* hs   = (const float*)d_in[0];  // (4,4096,4096) fp32
    const float* w    = (const float*)d_in[1];  // (256,4096)    fp32
    const float* bias = (const float*)d_in[2];  // (256,)        fp32

    dim3 grid(NEXP / BN, T_TOK / BM);
    gemm_kernel<<<grid, 256>>>(hs, w);

    const int mode = (out_size >= 2 * T_TOK * TOPK) ? 0 : 1;
    route_kernel<<<T_TOK / 8, 256>>>(bias, d_out, mode);
}

// round 4
// speedup vs baseline: 2.4635x; 2.4635x over previous
#include <cuda_runtime.h>
#include <math.h>
#include <stdint.h>

#define T_TOK 16384
#define HDIM  4096
#define NEXP  256
#define TOPK  8
#define TOPK_GRP 4

#define BM 128
#define BN 128
#define KC 32                 // floats per k-chunk
#define NCHUNK (HDIM / KC)    // 128
#define THREADS 512

// stage: AH(16K) AL(16K) BH(16K) BL(16K) = 64KB; 2 stages = 128KB
#define AH_OFF 0
#define AL_OFF 16384
#define BH_OFF 32768
#define BL_OFF 49152
#define STAGE_BYTES 65536
#define SM_TOTAL (2 * STAGE_BYTES)

__device__ float g_logits[(size_t)T_TOK * NEXP];

// ---------------- PTX helpers ----------------
__device__ __forceinline__ uint32_t smem_u32(const void* p) {
    uint32_t a;
    asm("{ .reg .u64 t; cvta.to.shared.u64 t, %1; cvt.u32.u64 %0, t; }" : "=r"(a) : "l"(p));
    return a;
}
__device__ __forceinline__ uint32_t tf32c(float x) {
    uint32_t u;
    asm("cvt.rna.tf32.f32 %0, %1;" : "=r"(u) : "f"(x));
    return u;
}
__device__ __forceinline__ void sts128(uint32_t addr, uint32_t x, uint32_t y,
                                       uint32_t z, uint32_t w) {
    asm volatile("st.shared.v4.b32 [%0], {%1, %2, %3, %4};"
                 :: "r"(addr), "r"(x), "r"(y), "r"(z), "r"(w) : "memory");
}
__device__ __forceinline__ void ldsm4(uint32_t* r, uint32_t addr) {
    asm volatile("ldmatrix.sync.aligned.m8n8.x4.shared.b16 {%0, %1, %2, %3}, [%4];"
                 : "=r"(r[0]), "=r"(r[1]), "=r"(r[2]), "=r"(r[3]) : "r"(addr));
}
__device__ __forceinline__ void mma_tf32(float* c, const uint32_t* a,
                                         uint32_t b0, uint32_t b1) {
    asm volatile(
        "mma.sync.aligned.m16n8k8.row.col.f32.tf32.tf32.f32 "
        "{%0, %1, %2, %3}, {%4, %5, %6, %7}, {%8, %9}, {%0, %1, %2, %3};"
        : "+f"(c[0]), "+f"(c[1]), "+f"(c[2]), "+f"(c[3])
        : "r"(a[0]), "r"(a[1]), "r"(a[2]), "r"(a[3]), "r"(b0), "r"(b1));
}
__device__ __forceinline__ void cvt_sts(uint32_t addr_hi, uint32_t addr_lo, float4 v) {
    uint32_t hx = tf32c(v.x), hy = tf32c(v.y), hz = tf32c(v.z), hw = tf32c(v.w);
    float lx = v.x - __uint_as_float(hx);
    float ly = v.y - __uint_as_float(hy);
    float lz = v.z - __uint_as_float(hz);
    float lw = v.w - __uint_as_float(hw);
    sts128(addr_hi, hx, hy, hz, hw);
    sts128(addr_lo, tf32c(lx), tf32c(ly), tf32c(lz), tf32c(lw));
}

// ---------------------------------------------------------------------------
// tf32x3 GEMM, two-level accumulation (MMA partials zeroed every 64 k):
// grid (2,128); 512 threads; 16 warps; warp tile 32x32
// ---------------------------------------------------------------------------
__global__ __launch_bounds__(THREADS, 1) void gemm_mma(const float* __restrict__ A,
                                                       const float* __restrict__ W) {
    extern __shared__ char smem[];
    const uint32_t sb = smem_u32(smem);
    const int tid  = threadIdx.x;
    const int lane = tid & 31;
    const int wid  = tid >> 5;
    const int wm   = wid & 3;   // 4 m-tiles of 32 rows
    const int wn   = wid >> 2;  // 4 n-tiles of 32 cols

    // ---- producer mapping: row = tid>>2, 8-float granule = tid&3 ----
    const int trow = tid >> 2;
    const int tseg = tid & 3;
    const float* pa = A + (size_t)(blockIdx.y * BM + trow) * HDIM + tseg * 8;
    const float* pb = W + (size_t)(blockIdx.x * BN + trow) * HDIM + tseg * 8;

    uint32_t sts_off[2];
#pragma unroll
    for (int i = 0; i < 2; i++) {
        int s16 = tseg * 2 + i;
        sts_off[i] = (uint32_t)(trow * 128 + (((s16 ^ (trow & 7)) & 7) << 4));
    }

    // ---- ldmatrix lane addressing ----
    const int r  = lane & 7;
    const int j  = lane >> 3;
    const int jr = j & 1;
    const int jk = j >> 1;
    const int arow = wm * 32 + r + jr * 8;   // + mi*16
    const int brow = wn * 32 + r + jk * 8;   // + q*16

    float macc[2][4][4];   // master (RN FADD accumulation)
    float bacc[2][4][4];   // per-64k MMA block accumulator
#pragma unroll
    for (int mi = 0; mi < 2; mi++)
#pragma unroll
        for (int nj = 0; nj < 4; nj++)
#pragma unroll
            for (int q = 0; q < 4; q++) { macc[mi][nj][q] = 0.0f; bacc[mi][nj][q] = 0.0f; }

    // prefetch + store chunk 0
    float4 va0 = *(const float4*)(pa + 0);
    float4 va1 = *(const float4*)(pa + 4);
    float4 vb0 = *(const float4*)(pb + 0);
    float4 vb1 = *(const float4*)(pb + 4);
    cvt_sts(sb + AH_OFF + sts_off[0], sb + AL_OFF + sts_off[0], va0);
    cvt_sts(sb + AH_OFF + sts_off[1], sb + AL_OFF + sts_off[1], va1);
    cvt_sts(sb + BH_OFF + sts_off[0], sb + BL_OFF + sts_off[0], vb0);
    cvt_sts(sb + BH_OFF + sts_off[1], sb + BL_OFF + sts_off[1], vb1);
    __syncthreads();

    for (int c = 0; c < NCHUNK; c++) {
        const uint32_t st = sb + (uint32_t)((c & 1) * STAGE_BYTES);

        if (c + 1 < NCHUNK) {
            const float* qa = pa + (c + 1) * KC;
            const float* qb = pb + (c + 1) * KC;
            va0 = *(const float4*)(qa + 0);
            va1 = *(const float4*)(qa + 4);
            vb0 = *(const float4*)(qb + 0);
            vb1 = *(const float4*)(qb + 4);
        }

#pragma unroll
        for (int k8 = 0; k8 < 4; k8++) {
            const uint32_t asg = (uint32_t)(((k8 * 2 + jk) ^ r) << 4);
            const uint32_t bsg = (uint32_t)(((k8 * 2 + jr) ^ r) << 4);

            uint32_t ah[2][4], al[2][4], bh[2][4], bl[2][4];
#pragma unroll
            for (int mi = 0; mi < 2; mi++) {
                const uint32_t ra = (uint32_t)((arow + mi * 16) * 128) + asg;
                ldsm4(ah[mi], st + AH_OFF + ra);
                ldsm4(al[mi], st + AL_OFF + ra);
            }
#pragma unroll
            for (int q = 0; q < 2; q++) {
                const uint32_t rb = (uint32_t)((brow + q * 16) * 128) + bsg;
                ldsm4(bh[q], st + BH_OFF + rb);
                ldsm4(bl[q], st + BL_OFF + rb);
            }
            // term-major order: 8 independent accumulators between reuses
#pragma unroll
            for (int mi = 0; mi < 2; mi++)
#pragma unroll
                for (int nj = 0; nj < 4; nj++) {
                    const int q = nj >> 1, s2 = (nj & 1) * 2;
                    mma_tf32(bacc[mi][nj], ah[mi], bh[q][s2], bh[q][s2 + 1]);
                }
#pragma unroll
            for (int mi = 0; mi < 2; mi++)
#pragma unroll
                for (int nj = 0; nj < 4; nj++) {
                    const int q = nj >> 1, s2 = (nj & 1) * 2;
                    mma_tf32(bacc[mi][nj], ah[mi], bl[q][s2], bl[q][s2 + 1]);
                }
#pragma unroll
            for (int mi = 0; mi < 2; mi++)
#pragma unroll
                for (int nj = 0; nj < 4; nj++) {
                    const int q = nj >> 1, s2 = (nj & 1) * 2;
                    mma_tf32(bacc[mi][nj], al[mi], bh[q][s2], bh[q][s2 + 1]);
                }
        }

        // fold MMA block into master every 2 chunks (k=64), reset block
        if (c & 1) {
#pragma unroll
            for (int mi = 0; mi < 2; mi++)
#pragma unroll
                for (int nj = 0; nj < 4; nj++)
#pragma unroll
                    for (int q = 0; q < 4; q++) {
                        macc[mi][nj][q] += bacc[mi][nj][q];
                        bacc[mi][nj][q] = 0.0f;
                    }
        }

        if (c + 1 < NCHUNK) {
            const uint32_t nst = sb + (uint32_t)(((c + 1) & 1) * STAGE_BYTES);
            cvt_sts(nst + AH_OFF + sts_off[0], nst + AL_OFF + sts_off[0], va0);
            cvt_sts(nst + AH_OFF + sts_off[1], nst + AL_OFF + sts_off[1], va1);
            cvt_sts(nst + BH_OFF + sts_off[0], nst + BL_OFF + sts_off[0], vb0);
            cvt_sts(nst + BH_OFF + sts_off[1], nst + BL_OFF + sts_off[1], vb1);
            __syncthreads();
        }
    }

    // ---- epilogue ----
    const int g = lane >> 2, t = lane & 3;
#pragma unroll
    for (int mi = 0; mi < 2; mi++) {
        const int grow = blockIdx.y * BM + wm * 32 + mi * 16 + g;
#pragma unroll
        for (int nj = 0; nj < 4; nj++) {
            const int gcol = blockIdx.x * BN + wn * 32 + (nj >> 1) * 16 + (nj & 1) * 8 + 2 * t;
            float2 v0 = make_float2(macc[mi][nj][0], macc[mi][nj][1]);
            float2 v1 = make_float2(macc[mi][nj][2], macc[mi][nj][3]);
            *(float2*)&g_logits[(size_t)grow * NEXP + gcol]       = v0;
            *(float2*)&g_logits[(size_t)(grow + 8) * NEXP + gcol] = v1;
        }
    }
}

// ---------------------------------------------------------------------------
// Routing: one warp per token (unchanged, verified correct)
// ---------------------------------------------------------------------------
__global__ __launch_bounds__(256) void route_kernel(const float* __restrict__ bias,
                                                    void* __restrict__ out,
                                                    int mode) {
    const int warp = (blockIdx.x * blockDim.x + threadIdx.x) >> 5;
    const int lane = threadIdx.x & 31;
    if (warp >= T_TOK) return;

    const float* lg = g_logits + (size_t)warp * NEXP + lane * 8;
    float4 x0 = *(const float4*)lg;
    float4 x1 = *(const float4*)(lg + 4);
    float xs[8] = {x0.x, x0.y, x0.z, x0.w, x1.x, x1.y, x1.z, x1.w};

    const float* bp = bias + lane * 8;
    float4 b0 = *(const float4*)bp;
    float4 b1 = *(const float4*)(bp + 4);
    float bs[8] = {b0.x, b0.y, b0.z, b0.w, b1.x, b1.y, b1.z, b1.w};

    float s[8], sc[8];
#pragma unroll
    for (int jj = 0; jj < 8; jj++) {
        s[jj]  = 1.0f / (1.0f + expf(-xs[jj]));
        sc[jj] = s[jj] + bs[jj];
    }

    float m1 = -1e30f, m2 = -1e30f;
#pragma unroll
    for (int jj = 0; jj < 8; jj++) {
        float x = sc[jj];
        if (x > m1) { m2 = m1; m1 = x; }
        else if (x > m2) { m2 = x; }
    }
#pragma unroll
    for (int d = 1; d <= 2; d <<= 1) {
        float o1 = __shfl_xor_sync(0xffffffffu, m1, d);
        float o2 = __shfl_xor_sync(0xffffffffu, m2, d);
        float n2 = fmaxf(fminf(m1, o1), fmaxf(m2, o2));
        m1 = fmaxf(m1, o1);
        m2 = n2;
    }
    float gs = m1 + m2;

    float gsv[8];
#pragma unroll
    for (int gg = 0; gg < 8; gg++) gsv[gg] = __shfl_sync(0xffffffffu, gs, gg * 4);

    unsigned gsel = 0;
#pragma unroll
    for (int rr = 0; rr < TOPK_GRP; rr++) {
        float best = -1e30f; int bi = 0;
#pragma unroll
        for (int gg = 0; gg < 8; gg++) {
            float v = ((gsel >> gg) & 1u) ? -1e30f : gsv[gg];
            if (v > best) { best = v; bi = gg; }
        }
        gsel |= 1u << bi;
    }

    const bool insel = (gsel >> (lane >> 2)) & 1u;
    float mv[8];
#pragma unroll
    for (int jj = 0; jj < 8; jj++) mv[jj] = insel ? sc[jj] : 0.0f;

    int   oi[8];
    float ow[8];
#pragma unroll
    for (int rr = 0; rr < TOPK; rr++) {
        float lb = mv[0]; int lj = 0;
#pragma unroll
        for (int jj = 1; jj < 8; jj++)
            if (mv[jj] > lb) { lb = mv[jj]; lj = jj; }
        float bv = lb;
        int   be = lane * 8 + lj;
#pragma unroll
        for (int off = 16; off >= 1; off >>= 1) {
            float ov = __shfl_xor_sync(0xffffffffu, bv, off);
            int   oe = __shfl_xor_sync(0xffffffffu, be, off);
            if (ov > bv || (ov == bv && oe < be)) { bv = ov; be = oe; }
        }
        oi[rr] = be;
        const int jj2 = be & 7;
        float sj = s[0];
#pragma unroll
        for (int jj = 1; jj < 8; jj++)
            if (jj2 == jj) sj = s[jj];
        ow[rr] = __shfl_sync(0xffffffffu, sj, be >> 3);
        if (lane == (be >> 3)) {
#pragma unroll
            for (int jj = 0; jj < 8; jj++)
                if (jj2 == jj) mv[jj] = -1e30f;
        }
    }

    if (lane == 0) {
        float sum = 0.0f;
#pragma unroll
        for (int rr = 0; rr < TOPK; rr++) sum += ow[rr];
        const float den = sum + 1e-20f;
        if (mode == 0) {
            float* of = (float*)out;
#pragma unroll
            for (int rr = 0; rr < TOPK; rr++) {
                of[(size_t)warp * TOPK + rr] = (float)oi[rr];
                of[(size_t)T_TOK * TOPK + (size_t)warp * TOPK + rr] =
                    (ow[rr] / den) * 2.5f;
            }
        } else {
            int* op = (int*)out;
#pragma unroll
            for (int rr = 0; rr < TOPK; rr++) op[(size_t)warp * TOPK + rr] = oi[rr];
        }
    }
}

extern "C" void kernel_launch(void* const* d_in, const int* in_sizes, int n_in,
                              void* d_out, int out_size) {
    const float* hs   = (const float*)d_in[0];
    const float* w    = (const float*)d_in[1];
    const float* bias = (const float*)d_in[2];

    cudaFuncSetAttribute(gemm_mma, cudaFuncAttributeMaxDynamicSharedMemorySize, SM_TOTAL);
    dim3 grid(NEXP / BN, T_TOK / BM);
    gemm_mma<<<grid, THREADS, SM_TOTAL>>>(hs, w);

    const int mode = (out_size >= 2 * T_TOK * TOPK) ? 0 : 1;
    route_kernel<<<T_TOK / 8, 256>>>(bias, d_out, mode);
}

// round 5
// speedup vs baseline: 3.5909x; 1.4577x over previous
#include <cuda_runtime.h>
#include <cuda_fp16.h>
#include <math.h>
#include <stdint.h>

#define T_TOK 16384
#define HDIM  4096
#define NEXP  256
#define TOPK  8
#define TOPK_GRP 4

#define BM 128
#define BN 128
#define KC 64                 // floats per k-chunk (fp16 row = 128B, SW128)
#define NCHUNK (HDIM / KC)    // 64
#define THREADS 512

// stage: AH(16K) AL(16K) BH(16K) BL(16K) = 64KB; 2 stages = 128KB
#define AH_OFF 0
#define AL_OFF 16384
#define BH_OFF 32768
#define BL_OFF 49152
#define STAGE_BYTES 65536
#define SM_TOTAL (2 * STAGE_BYTES)

__device__ float g_logits[(size_t)T_TOK * NEXP];

// ---------------- helpers ----------------
__device__ __forceinline__ uint32_t smem_u32(const void* p) {
    uint32_t a;
    asm("{ .reg .u64 t; cvta.to.shared.u64 t, %1; cvt.u32.u64 %0, t; }" : "=r"(a) : "l"(p));
    return a;
}
__device__ __forceinline__ void sts128(uint32_t addr, uint32_t x, uint32_t y,
                                       uint32_t z, uint32_t w) {
    asm volatile("st.shared.v4.b32 [%0], {%1, %2, %3, %4};"
                 :: "r"(addr), "r"(x), "r"(y), "r"(z), "r"(w) : "memory");
}
__device__ __forceinline__ void ldsm4(uint32_t* r, uint32_t addr) {
    asm volatile("ldmatrix.sync.aligned.m8n8.x4.shared.b16 {%0, %1, %2, %3}, [%4];"
                 : "=r"(r[0]), "=r"(r[1]), "=r"(r[2]), "=r"(r[3]) : "r"(addr));
}
__device__ __forceinline__ void mma_f16(float* c, const uint32_t* a,
                                        uint32_t b0, uint32_t b1) {
    asm volatile(
        "mma.sync.aligned.m16n8k16.row.col.f32.f16.f16.f32 "
        "{%0, %1, %2, %3}, {%4, %5, %6, %7}, {%8, %9}, {%0, %1, %2, %3};"
        : "+f"(c[0]), "+f"(c[1]), "+f"(c[2]), "+f"(c[3])
        : "r"(a[0]), "r"(a[1]), "r"(a[2]), "r"(a[3]), "r"(b0), "r"(b1));
}
// split two floats into packed fp16 hi pair + fp16 lo (residual) pair
__device__ __forceinline__ void split2(float a, float b, uint32_t& h, uint32_t& l) {
    __half ha = __float2half_rn(a), hb = __float2half_rn(b);
    float ra = a - __half2float(ha);
    float rb = b - __half2float(hb);
    __half2 ph = __halves2half2(ha, hb);
    __half2 pl = __halves2half2(__float2half_rn(ra), __float2half_rn(rb));
    h = *reinterpret_cast<uint32_t*>(&ph);
    l = *reinterpret_cast<uint32_t*>(&pl);
}
// convert 8 floats -> 4 hi u32 + 4 lo u32, then 2x STS.128
__device__ __forceinline__ void cvt_sts8(uint32_t addr_hi, uint32_t addr_lo,
                                         float4 v0, float4 v1) {
    uint32_t h[4], l[4];
    split2(v0.x, v0.y, h[0], l[0]);
    split2(v0.z, v0.w, h[1], l[1]);
    split2(v1.x, v1.y, h[2], l[2]);
    split2(v1.z, v1.w, h[3], l[3]);
    sts128(addr_hi, h[0], h[1], h[2], h[3]);
    sts128(addr_lo, l[0], l[1], l[2], l[3]);
}

// ---------------------------------------------------------------------------
// fp16x3 GEMM: logits[m][e] = dot(x[m,:], W[e,:]); W pre-scaled x64 (exact),
// logits descaled 1/64 at epilogue. Two-level accumulation (fold every 128 k).
// grid (2,128); 512 threads; 16 warps; warp tile 32x32
// ---------------------------------------------------------------------------
__global__ __launch_bounds__(THREADS) void gemm_mma(const float* __restrict__ A,
                                                    const float* __restrict__ W) {
    extern __shared__ char smem[];
    const uint32_t sb = smem_u32(smem);
    const int tid  = threadIdx.x;
    const int lane = tid & 31;
    const int wid  = tid >> 5;
    const int wm   = wid & 3;   // 4 m-tiles of 32 rows
    const int wn   = wid >> 2;  // 4 n-tiles of 32 cols

    // ---- producer mapping: row = tid>>2, 16-float seg = tid&3 ----
    const int prow = tid >> 2;
    const int pseg = tid & 3;                 // 16 floats each
    const float* pa = A + (size_t)(blockIdx.y * BM + prow) * HDIM + pseg * 16;
    const float* pb = W + (size_t)(blockIdx.x * BN + prow) * HDIM + pseg * 16;

    // swizzled STS addresses for the two 16B fp16 granules (8 floats each)
    uint32_t sts_off[2];
#pragma unroll
    for (int i = 0; i < 2; i++) {
        int g = pseg * 2 + i;
        sts_off[i] = (uint32_t)(prow * 128 + (((g ^ (prow & 7)) & 7) << 4));
    }

    // ---- ldmatrix lane addressing ----
    const int r  = lane & 7;
    const int j  = lane >> 3;
    const int jr = j & 1;       // A: row-half, B: k-half
    const int jk = j >> 1;      // A: k-half,  B: n-half
    const int arow = wm * 32 + r + jr * 8;        // + mi*16 (doesn't change &7)
    const int brow = wn * 32 + r + jk * 8;        // + q*16
    const uint32_t axr = (uint32_t)(arow & 7);
    const uint32_t bxr = (uint32_t)(brow & 7);
    const uint32_t abase = (uint32_t)(arow * 128);
    const uint32_t bbase = (uint32_t)(brow * 128);

    float macc[2][4][4];   // master (RN FADD)
    float bacc[2][4][4];   // per-128k HW-accumulated block
#pragma unroll
    for (int mi = 0; mi < 2; mi++)
#pragma unroll
        for (int nj = 0; nj < 4; nj++)
#pragma unroll
            for (int q = 0; q < 4; q++) { macc[mi][nj][q] = 0.0f; bacc[mi][nj][q] = 0.0f; }

    // ---- preload chunk 0 ----
    {
        float4 a0 = *(const float4*)(pa + 0), a1 = *(const float4*)(pa + 4);
        float4 a2 = *(const float4*)(pa + 8), a3 = *(const float4*)(pa + 12);
        float4 b0 = *(const float4*)(pb + 0), b1 = *(const float4*)(pb + 4);
        float4 b2 = *(const float4*)(pb + 8), b3 = *(const float4*)(pb + 12);
        // scale W by 64 (exact)
        b0.x *= 64.f; b0.y *= 64.f; b0.z *= 64.f; b0.w *= 64.f;
        b1.x *= 64.f; b1.y *= 64.f; b1.z *= 64.f; b1.w *= 64.f;
        b2.x *= 64.f; b2.y *= 64.f; b2.z *= 64.f; b2.w *= 64.f;
        b3.x *= 64.f; b3.y *= 64.f; b3.z *= 64.f; b3.w *= 64.f;
        cvt_sts8(sb + AH_OFF + sts_off[0], sb + AL_OFF + sts_off[0], a0, a1);
        cvt_sts8(sb + AH_OFF + sts_off[1], sb + AL_OFF + sts_off[1], a2, a3);
        cvt_sts8(sb + BH_OFF + sts_off[0], sb + BL_OFF + sts_off[0], b0, b1);
        cvt_sts8(sb + BH_OFF + sts_off[1], sb + BL_OFF + sts_off[1], b2, b3);
    }
    __syncthreads();

    for (int c = 0; c < NCHUNK; c++) {
        const uint32_t st = sb + (uint32_t)((c & 1) * STAGE_BYTES);
        const bool more = (c + 1 < NCHUNK);

        // prefetch A for next chunk (regs live through first half of MMAs)
        float4 va[4];
        if (more) {
            const float* qa = pa + (c + 1) * KC;
#pragma unroll
            for (int i = 0; i < 4; i++) va[i] = *(const float4*)(qa + i * 4);
        }

#pragma unroll
        for (int k16 = 0; k16 < 2; k16++) {
            uint32_t ah[2][4], al[2][4], bh[2][4], bl[2][4];
            const uint32_t asg = (uint32_t)(((k16 * 2 + jk) ^ axr) << 4);
            const uint32_t bsg = (uint32_t)(((k16 * 2 + jr) ^ bxr) << 4);
#pragma unroll
            for (int mi = 0; mi < 2; mi++) {
                const uint32_t ra = abase + (uint32_t)(mi * 2048) + asg;
                ldsm4(ah[mi], st + AH_OFF + ra);
                ldsm4(al[mi], st + AL_OFF + ra);
            }
#pragma unroll
            for (int q = 0; q < 2; q++) {
                const uint32_t rb = bbase + (uint32_t)(q * 2048) + bsg;
                ldsm4(bh[q], st + BH_OFF + rb);
                ldsm4(bl[q], st + BL_OFF + rb);
            }
#pragma unroll
            for (int mi = 0; mi < 2; mi++)
#pragma unroll
                for (int nj = 0; nj < 4; nj++) {
                    const int q = nj >> 1, s2 = (nj & 1) * 2;
                    mma_f16(bacc[mi][nj], ah[mi], bh[q][s2], bh[q][s2 + 1]);
                }
#pragma unroll
            for (int mi = 0; mi < 2; mi++)
#pragma unroll
                for (int nj = 0; nj < 4; nj++) {
                    const int q = nj >> 1, s2 = (nj & 1) * 2;
                    mma_f16(bacc[mi][nj], ah[mi], bl[q][s2], bl[q][s2 + 1]);
                }
#pragma unroll
            for (int mi = 0; mi < 2; mi++)
#pragma unroll
                for (int nj = 0; nj < 4; nj++) {
                    const int q = nj >> 1, s2 = (nj & 1) * 2;
                    mma_f16(bacc[mi][nj], al[mi], bh[q][s2], bh[q][s2 + 1]);
                }
        }

        // prefetch B for next chunk
        float4 vb[4];
        if (more) {
            const float* qb = pb + (c + 1) * KC;
#pragma unroll
            for (int i = 0; i < 4; i++) vb[i] = *(const float4*)(qb + i * 4);
        }

#pragma unroll
        for (int k16 = 2; k16 < 4; k16++) {
            uint32_t ah[2][4], al[2][4], bh[2][4], bl[2][4];
            const uint32_t asg = (uint32_t)(((k16 * 2 + jk) ^ axr) << 4);
            const uint32_t bsg = (uint32_t)(((k16 * 2 + jr) ^ bxr) << 4);
#pragma unroll
            for (int mi = 0; mi < 2; mi++) {
                const uint32_t ra = abase + (uint32_t)(mi * 2048) + asg;
                ldsm4(ah[mi], st + AH_OFF + ra);
                ldsm4(al[mi], st + AL_OFF + ra);
            }
#pragma unroll
            for (int q = 0; q < 2; q++) {
                const uint32_t rb = bbase + (uint32_t)(q * 2048) + bsg;
                ldsm4(bh[q], st + BH_OFF + rb);
                ldsm4(bl[q], st + BL_OFF + rb);
            }
#pragma unroll
            for (int mi = 0; mi < 2; mi++)
#pragma unroll
                for (int nj = 0; nj < 4; nj++) {
                    const int q = nj >> 1, s2 = (nj & 1) * 2;
                    mma_f16(bacc[mi][nj], ah[mi], bh[q][s2], bh[q][s2 + 1]);
                }
#pragma unroll
            for (int mi = 0; mi < 2; mi++)
#pragma unroll
                for (int nj = 0; nj < 4; nj++) {
                    const int q = nj >> 1, s2 = (nj & 1) * 2;
                    mma_f16(bacc[mi][nj], ah[mi], bl[q][s2], bl[q][s2 + 1]);
                }
#pragma unroll
            for (int mi = 0; mi < 2; mi++)
#pragma unroll
                for (int nj = 0; nj < 4; nj++) {
                    const int q = nj >> 1, s2 = (nj & 1) * 2;
                    mma_f16(bacc[mi][nj], al[mi], bh[q][s2], bh[q][s2 + 1]);
                }
        }

        // fold HW block into master every 2 chunks (k=128)
        if (c & 1) {
#pragma unroll
            for (int mi = 0; mi < 2; mi++)
#pragma unroll
                for (int nj = 0; nj < 4; nj++)
#pragma unroll
                    for (int q = 0; q < 4; q++) {
                        macc[mi][nj][q] += bacc[mi][nj][q];
                        bacc[mi][nj][q] = 0.0f;
                    }
        }

        if (more) {
            const uint32_t nst = sb + (uint32_t)(((c + 1) & 1) * STAGE_BYTES);
#pragma unroll
            for (int i = 0; i < 4; i++) {
                vb[i].x *= 64.f; vb[i].y *= 64.f; vb[i].z *= 64.f; vb[i].w *= 64.f;
            }
            cvt_sts8(nst + AH_OFF + sts_off[0], nst + AL_OFF + sts_off[0], va[0], va[1]);
            cvt_sts8(nst + AH_OFF + sts_off[1], nst + AL_OFF + sts_off[1], va[2], va[3]);
            cvt_sts8(nst + BH_OFF + sts_off[0], nst + BL_OFF + sts_off[0], vb[0], vb[1]);
            cvt_sts8(nst + BH_OFF + sts_off[1], nst + BL_OFF + sts_off[1], vb[2], vb[3]);
            __syncthreads();
        }
    }

    // ---- epilogue: descale by 1/64 and write ----
    const int g = lane >> 2, t = lane & 3;
#pragma unroll
    for (int mi = 0; mi < 2; mi++) {
        const int grow = blockIdx.y * BM + wm * 32 + mi * 16 + g;
#pragma unroll
        for (int nj = 0; nj < 4; nj++) {
            const int gcol = blockIdx.x * BN + wn * 32 + (nj >> 1) * 16 + (nj & 1) * 8 + 2 * t;
            float2 v0 = make_float2(macc[mi][nj][0] * 0.015625f, macc[mi][nj][1] * 0.015625f);
            float2 v1 = make_float2(macc[mi][nj][2] * 0.015625f, macc[mi][nj][3] * 0.015625f);
            *(float2*)&g_logits[(size_t)grow * NEXP + gcol]       = v0;
            *(float2*)&g_logits[(size_t)(grow + 8) * NEXP + gcol] = v1;
        }
    }
}

// ---------------------------------------------------------------------------
// Routing: one warp per token (unchanged, verified correct)
// ---------------------------------------------------------------------------
__global__ __launch_bounds__(256) void route_kernel(const float* __restrict__ bias,
                                                    void* __restrict__ out,
                                                    int mode) {
    const int warp = (blockIdx.x * blockDim.x + threadIdx.x) >> 5;
    const int lane = threadIdx.x & 31;
    if (warp >= T_TOK) return;

    const float* lg = g_logits + (size_t)warp * NEXP + lane * 8;
    float4 x0 = *(const float4*)lg;
    float4 x1 = *(const float4*)(lg + 4);
    float xs[8] = {x0.x, x0.y, x0.z, x0.w, x1.x, x1.y, x1.z, x1.w};

    const float* bp = bias + lane * 8;
    float4 b0 = *(const float4*)bp;
    float4 b1 = *(const float4*)(bp + 4);
    float bs[8] = {b0.x, b0.y, b0.z, b0.w, b1.x, b1.y, b1.z, b1.w};

    float s[8], sc[8];
#pragma unroll
    for (int jj = 0; jj < 8; jj++) {
        s[jj]  = 1.0f / (1.0f + expf(-xs[jj]));
        sc[jj] = s[jj] + bs[jj];
    }

    float m1 = -1e30f, m2 = -1e30f;
#pragma unroll
    for (int jj = 0; jj < 8; jj++) {
        float x = sc[jj];
        if (x > m1) { m2 = m1; m1 = x; }
        else if (x > m2) { m2 = x; }
    }
#pragma unroll
    for (int d = 1; d <= 2; d <<= 1) {
        float o1 = __shfl_xor_sync(0xffffffffu, m1, d);
        float o2 = __shfl_xor_sync(0xffffffffu, m2, d);
        float n2 = fmaxf(fminf(m1, o1), fmaxf(m2, o2));
        m1 = fmaxf(m1, o1);
        m2 = n2;
    }
    float gs = m1 + m2;

    float gsv[8];
#pragma unroll
    for (int gg = 0; gg < 8; gg++) gsv[gg] = __shfl_sync(0xffffffffu, gs, gg * 4);

    unsigned gsel = 0;
#pragma unroll
    for (int rr = 0; rr < TOPK_GRP; rr++) {
        float best = -1e30f; int bi = 0;
#pragma unroll
        for (int gg = 0; gg < 8; gg++) {
            float v = ((gsel >> gg) & 1u) ? -1e30f : gsv[gg];
            if (v > best) { best = v; bi = gg; }
        }
        gsel |= 1u << bi;
    }

    const bool insel = (gsel >> (lane >> 2)) & 1u;
    float mv[8];
#pragma unroll
    for (int jj = 0; jj < 8; jj++) mv[jj] = insel ? sc[jj] : 0.0f;

    int   oi[8];
    float ow[8];
#pragma unroll
    for (int rr = 0; rr < TOPK; rr++) {
        float lb = mv[0]; int lj = 0;
#pragma unroll
        for (int jj = 1; jj < 8; jj++)
            if (mv[jj] > lb) { lb = mv[jj]; lj = jj; }
        float bv = lb;
        int   be = lane * 8 + lj;
#pragma unroll
        for (int off = 16; off >= 1; off >>= 1) {
            float ov = __shfl_xor_sync(0xffffffffu, bv, off);
            int   oe = __shfl_xor_sync(0xffffffffu, be, off);
            if (ov > bv || (ov == bv && oe < be)) { bv = ov; be = oe; }
        }
        oi[rr] = be;
        const int jj2 = be & 7;
        float sj = s[0];
#pragma unroll
        for (int jj = 1; jj < 8; jj++)
            if (jj2 == jj) sj = s[jj];
        ow[rr] = __shfl_sync(0xffffffffu, sj, be >> 3);
        if (lane == (be >> 3)) {
#pragma unroll
            for (int jj = 0; jj < 8; jj++)
                if (jj2 == jj) mv[jj] = -1e30f;
        }
    }

    if (lane == 0) {
        float sum = 0.0f;
#pragma unroll
        for (int rr = 0; rr < TOPK; rr++) sum += ow[rr];
        const float den = sum + 1e-20f;
        if (mode == 0) {
            float* of = (float*)out;
#pragma unroll
            for (int rr = 0; rr < TOPK; rr++) {
                of[(size_t)warp * TOPK + rr] = (float)oi[rr];
                of[(size_t)T_TOK * TOPK + (size_t)warp * TOPK + rr] =
                    (ow[rr] / den) * 2.5f;
            }
        } else {
            int* op = (int*)out;
#pragma unroll
            for (int rr = 0; rr < TOPK; rr++) op[(size_t)warp * TOPK + rr] = oi[rr];
        }
    }
}

extern "C" void kernel_launch(void* const* d_in, const int* in_sizes, int n_in,
                              void* d_out, int out_size) {
    const float* hs   = (const float*)d_in[0];
    const float* w    = (const float*)d_in[1];
    const float* bias = (const float*)d_in[2];

    cudaFuncSetAttribute(gemm_mma, cudaFuncAttributeMaxDynamicSharedMemorySize, SM_TOTAL);
    dim3 grid(NEXP / BN, T_TOK / BM);
    gemm_mma<<<grid, THREADS, SM_TOTAL>>>(hs, w);

    const int mode = (out_size >= 2 * T_TOK * TOPK) ? 0 : 1;
    route_kernel<<<T_TOK / 8, 256>>>(bias, d_out, mode);
}